// round 10
// baseline (speedup 1.0000x reference)
#include <cuda_runtime.h>
#include <math.h>

#define DIM 512
#define MARGIN 1.0f
#define RULE_WEIGHT 0.5f

#define MAX_B   1024
#define MAX_NEG 8192

// Scratch (allocation-free rule: __device__ globals)
__device__ float g_dposm[MAX_B];          // MARGIN + d_pos (pre-biased)
__device__ float g_dneg[MAX_NEG];
__device__ float g_rule_sum = 0.f;        // ~40 atomic adds; reset by last block
__device__ unsigned int g_ticket = 0;     // reset by last block

__device__ __forceinline__ float warp_red(float v) {
#pragma unroll
    for (int o = 16; o; o >>= 1) v += __shfl_xor_sync(0xffffffffu, v, o);
    return v;
}

// acq_rel ticket: release orders this block's prior global stores (already in
// L2 via write-through / __stcg) before the increment; the winner's acquire
// orders its subsequent loads. NO membar.gl => no CCTL.IVALL L1-flush storm.
__device__ __forceinline__ unsigned int ticket_acq_rel(unsigned int* p) {
    unsigned int old;
    asm volatile("atom.acq_rel.gpu.global.add.u32 %0, [%1], 1;"
                 : "=r"(old) : "l"(p) : "memory");
    return old;
}

// TransH distance, he/te register-resident (R1 variant — best measured).
// d = || (he - te + re) - c*w ||,  c = (he.w - te.w)/(w.w)
__device__ __forceinline__ float dist_from_regs(
    const float4 he[4], const float4 te[4],
    const float* __restrict__ rel, const float* __restrict__ nv,
    int r, int lane)
{
    const float4* w4  = reinterpret_cast<const float4*>(nv  + (size_t)r * DIM);
    const float4* re4 = reinterpret_cast<const float4*>(rel + (size_t)r * DIM);
    float4 w[4], re[4];
    float ww = 0.f, hw = 0.f, tw = 0.f;
#pragma unroll
    for (int i = 0; i < 4; i++) {
        w[i]  = w4[lane + 32 * i];
        re[i] = re4[lane + 32 * i];
        ww += w[i].x * w[i].x + w[i].y * w[i].y + w[i].z * w[i].z + w[i].w * w[i].w;
        hw += he[i].x * w[i].x + he[i].y * w[i].y + he[i].z * w[i].z + he[i].w * w[i].w;
        tw += te[i].x * w[i].x + te[i].y * w[i].y + te[i].z * w[i].z + te[i].w * w[i].w;
    }
    ww = warp_red(ww);
    hw = warp_red(hw);
    tw = warp_red(tw);
    float c = (hw - tw) / ww;
    float ss = 0.f;
#pragma unroll
    for (int i = 0; i < 4; i++) {
        float dx = he[i].x - te[i].x + re[i].x - c * w[i].x;
        float dy = he[i].y - te[i].y + re[i].y - c * w[i].y;
        float dz = he[i].z - te[i].z + re[i].z - c * w[i].z;
        float dw = he[i].w - te[i].w + re[i].w - c * w[i].w;
        ss += dx * dx + dy * dy + dz * dz + dw * dw;
    }
    ss = warp_red(ss);
    return sqrtf(ss);
}

__global__ void __launch_bounds__(256)
fused_all(const int* __restrict__ pos, const int* __restrict__ neg,
          const int* __restrict__ rr1, const int* __restrict__ rr2,
          const float* __restrict__ rconf,
          const float* __restrict__ ent, const float* __restrict__ rel,
          const float* __restrict__ nv,
          float* __restrict__ out,
          int B, int NEG, int NR)
{
    int tid  = threadIdx.x;
    int gw   = (blockIdx.x * blockDim.x + tid) >> 5;
    int lane = tid & 31;

    // ---- Phase 1: independent warp-per-distance (R1 structure) ----
    if (gw < B + NEG) {
        int h, r, t;
        bool is_pos = (gw < B);
        if (is_pos) {
            h = pos[3 * gw]; r = pos[3 * gw + 1]; t = pos[3 * gw + 2];
        } else {
            int k = gw - B;
            h = neg[3 * k]; r = neg[3 * k + 1]; t = neg[3 * k + 2];
        }

        const float4* he4 = reinterpret_cast<const float4*>(ent + (size_t)h * DIM);
        const float4* te4 = reinterpret_cast<const float4*>(ent + (size_t)t * DIM);
        float4 he[4], te[4];
#pragma unroll
        for (int i = 0; i < 4; i++) {
            he[i] = he4[lane + 32 * i];
            te[i] = te4[lane + 32 * i];
        }

        float d = dist_from_regs(he, te, rel, nv, r, lane);

        if (is_pos) {
            // Only rules with rule_r1[j] == r contribute (mask exact-zeros rest).
            float racc = 0.f;
            for (int j = 0; j < NR; j++) {
                if (rr1[j] == r)
                    racc += rconf[j] * dist_from_regs(he, te, rel, nv, rr2[j], lane);
            }
            if (lane == 0) {
                __stcg(&g_dposm[gw], MARGIN + d);         // L2-targeted store
                if (racc != 0.f) atomicAdd(&g_rule_sum, racc);  // ~40 warps
            }
        } else {
            if (lane == 0) __stcg(&g_dneg[gw - B], d);    // L2-targeted store
        }
    }

    // ---- Phase 2: acq_rel ticket (tid 0 only). No membar.gl anywhere. ----
    __syncthreads();
    __shared__ unsigned int s_last;
    if (tid == 0)
        s_last = (ticket_acq_rel(&g_ticket) == gridDim.x - 1) ? 1u : 0u;
    __syncthreads();
    if (!s_last) return;

    // ---- Phase 3: last block reduces. All reads __ldcg (L2-only) so L1
    //      staleness is structurally impossible; data is L2-hot. ----
    int ratio = NEG / B;
    float acc = 0.f;
    int nv4 = NEG >> 2;
    if ((ratio & 3) == 0) {
        int vpp = ratio >> 2;    // float4s of g_dneg per pos index
        const float4* n4 = reinterpret_cast<const float4*>(g_dneg);
        for (int q = tid; q < nv4; q += 256) {
            float4 v = __ldcg(&n4[q]);
            float pm = __ldcg(&g_dposm[q / vpp]);
            float v0 = pm - v.x; acc += (v0 > 0.f) ? v0 : 0.f;
            float v1 = pm - v.y; acc += (v1 > 0.f) ? v1 : 0.f;
            float v2 = pm - v.z; acc += (v2 > 0.f) ? v2 : 0.f;
            float v3 = pm - v.w; acc += (v3 > 0.f) ? v3 : 0.f;
        }
    } else {
        for (int k = tid; k < NEG; k += 256) {
            float v = __ldcg(&g_dposm[k / ratio]) - __ldcg(&g_dneg[k]);
            acc += (v > 0.f) ? v : 0.f;
        }
    }

    __shared__ float sb[256];
    sb[tid] = acc;
    __syncthreads();
    for (int s = 128; s; s >>= 1) {
        if (tid < s) sb[tid] += sb[tid + s];
        __syncthreads();
    }
    if (tid == 0) {
        float rs = __ldcg(&g_rule_sum);
        out[0] = sb[0] / (float)NEG + RULE_WEIGHT * rs;
        g_rule_sum = 0.f;        // reset for next graph replay (deterministic)
        g_ticket   = 0;
    }
}

extern "C" void kernel_launch(void* const* d_in, const int* in_sizes, int n_in,
                              void* d_out, int out_size)
{
    const int*   pos   = (const int*)d_in[0];
    const int*   neg   = (const int*)d_in[1];
    const int*   rr1   = (const int*)d_in[2];
    const int*   rr2   = (const int*)d_in[3];
    const float* rconf = (const float*)d_in[4];
    const float* ent   = (const float*)d_in[5];
    const float* rel   = (const float*)d_in[6];
    const float* nv    = (const float*)d_in[7];

    int B   = in_sizes[0] / 3;
    int NEG = in_sizes[1] / 3;
    int NR  = in_sizes[2];

    int totalWarps = B + NEG;
    int blocks = (totalWarps * 32 + 255) / 256;

    fused_all<<<blocks, 256>>>(pos, neg, rr1, rr2, rconf, ent, rel, nv,
                               (float*)d_out, B, NEG, NR);
}

// round 11
// speedup vs baseline: 1.3233x; 1.3233x over previous
#include <cuda_runtime.h>
#include <math.h>

#define DIM 512
#define MARGIN 1.0f
#define RULE_WEIGHT 0.5f

#define MAX_B   1024
#define MAX_NEG 8192

// Scratch (allocation-free rule: __device__ globals)
__device__ float g_dposm[MAX_B];        // MARGIN + d_pos (pre-biased)
__device__ float g_dneg[MAX_NEG];
__device__ float g_rule_sum = 0.f;      // ~40 atomic adds; reset by reduce blk0

__device__ __forceinline__ float warp_red(float v) {
#pragma unroll
    for (int o = 16; o; o >>= 1) v += __shfl_xor_sync(0xffffffffu, v, o);
    return v;
}

// TransH distance via expanded norm — SINGLE streaming pass over w and re,
// nothing but hd[4] + 4 accumulators stays register-resident.
//   u = hd + re
//   ||u - c*w||^2 = uu - 2c*uw + c^2*ww,   c = dw/ww  (dw = hd.w)
__device__ __forceinline__ float dist_lowreg(
    const float4 hd[4],
    const float* __restrict__ rel, const float* __restrict__ nv,
    int r, int lane)
{
    const float4* w4  = reinterpret_cast<const float4*>(nv  + (size_t)r * DIM);
    const float4* re4 = reinterpret_cast<const float4*>(rel + (size_t)r * DIM);
    float ww = 0.f, dw = 0.f, uu = 0.f, uw = 0.f;
#pragma unroll
    for (int i = 0; i < 4; i++) {
        float4 w  = w4[lane + 32 * i];
        float4 re = re4[lane + 32 * i];
        float ux = hd[i].x + re.x, uy = hd[i].y + re.y;
        float uz = hd[i].z + re.z, uq = hd[i].w + re.w;
        ww += w.x * w.x + w.y * w.y + w.z * w.z + w.w * w.w;
        dw += hd[i].x * w.x + hd[i].y * w.y + hd[i].z * w.z + hd[i].w * w.w;
        uu += ux * ux + uy * uy + uz * uz + uq * uq;
        uw += ux * w.x + uy * w.y + uz * w.z + uq * w.w;
    }
    ww = warp_red(ww);
    dw = warp_red(dw);
    uu = warp_red(uu);
    uw = warp_red(uw);
    float c = dw / ww;
    float ss = uu - 2.f * c * uw + c * c * ww;
    return sqrtf(fmaxf(ss, 0.f));
}

// Flat warp-per-task: [0,B) = pos triples (+rule terms), [B,B+NEG) = negs.
// Block 0/tid 0 zeroes out[0] so the reduce node can atomicAdd into it.
__global__ void __launch_bounds__(256)
dist_kernel(const int* __restrict__ pos, const int* __restrict__ neg,
            const int* __restrict__ rr1, const int* __restrict__ rr2,
            const float* __restrict__ rconf,
            const float* __restrict__ ent, const float* __restrict__ rel,
            const float* __restrict__ nv,
            float* __restrict__ out,
            int B, int NEG, int NR)
{
    if (blockIdx.x == 0 && threadIdx.x == 0) out[0] = 0.f;

    int gw   = (blockIdx.x * blockDim.x + threadIdx.x) >> 5;
    int lane = threadIdx.x & 31;
    if (gw >= B + NEG) return;

    int h, r, t;
    bool is_pos = (gw < B);
    if (is_pos) {
        h = pos[3 * gw]; r = pos[3 * gw + 1]; t = pos[3 * gw + 2];
    } else {
        int k = gw - B;
        h = neg[3 * k]; r = neg[3 * k + 1]; t = neg[3 * k + 2];
    }

    const float4* he4 = reinterpret_cast<const float4*>(ent + (size_t)h * DIM);
    const float4* te4 = reinterpret_cast<const float4*>(ent + (size_t)t * DIM);
    float4 hd[4];
#pragma unroll
    for (int i = 0; i < 4; i++) {
        float4 a = he4[lane + 32 * i];
        float4 b = te4[lane + 32 * i];
        hd[i].x = a.x - b.x; hd[i].y = a.y - b.y;
        hd[i].z = a.z - b.z; hd[i].w = a.w - b.w;
    }

    float d = dist_lowreg(hd, rel, nv, r, lane);

    if (is_pos) {
        // Only rules with rule_r1[j] == r contribute (mask exact-zeros the rest).
        float racc = 0.f;
        for (int j = 0; j < NR; j++) {
            if (rr1[j] == r)
                racc += rconf[j] * dist_lowreg(hd, rel, nv, rr2[j], lane);
        }
        if (lane == 0) {
            g_dposm[gw] = MARGIN + d;
            if (racc != 0.f) atomicAdd(&g_rule_sum, racc);   // ~40 warps hit
        }
    } else {
        if (lane == 0) g_dneg[gw - B] = d;
    }
}

// Multi-block one-shot reduce (validated in R9): each thread handles one
// float4 of g_dneg, block-reduces, atomicAdds into out. Block 0 folds the
// rule sum and resets it for the next graph replay.
__global__ void __launch_bounds__(256)
final_reduce(float* __restrict__ out, int B, int NEG)
{
    __shared__ float sb[256];
    int tid  = threadIdx.x;
    int gt   = blockIdx.x * blockDim.x + tid;
    int ratio = NEG / B;
    float inv_neg = 1.0f / (float)NEG;

    float acc = 0.f;
    int nv4 = NEG >> 2;
    if ((ratio & 3) == 0) {
        int vpp = ratio >> 2;   // float4s of g_dneg per pos index
        const float4* n4 = reinterpret_cast<const float4*>(g_dneg);
        for (int q = gt; q < nv4; q += gridDim.x * blockDim.x) {
            float4 v = n4[q];
            float pm = g_dposm[q / vpp];
            float v0 = pm - v.x; acc += (v0 > 0.f) ? v0 : 0.f;
            float v1 = pm - v.y; acc += (v1 > 0.f) ? v1 : 0.f;
            float v2 = pm - v.z; acc += (v2 > 0.f) ? v2 : 0.f;
            float v3 = pm - v.w; acc += (v3 > 0.f) ? v3 : 0.f;
        }
    } else {
        for (int k = gt; k < NEG; k += gridDim.x * blockDim.x) {
            float v = g_dposm[k / ratio] - g_dneg[k];
            acc += (v > 0.f) ? v : 0.f;
        }
    }

    sb[tid] = acc;
    __syncthreads();
    for (int s = 128; s; s >>= 1) {
        if (tid < s) sb[tid] += sb[tid + s];
        __syncthreads();
    }
    if (tid == 0) {
        float contrib = sb[0] * inv_neg;
        if (blockIdx.x == 0) {
            contrib += RULE_WEIGHT * g_rule_sum;
            g_rule_sum = 0.f;          // reset for next replay (deterministic)
        }
        atomicAdd(out, contrib);
    }
}

extern "C" void kernel_launch(void* const* d_in, const int* in_sizes, int n_in,
                              void* d_out, int out_size)
{
    const int*   pos   = (const int*)d_in[0];
    const int*   neg   = (const int*)d_in[1];
    const int*   rr1   = (const int*)d_in[2];
    const int*   rr2   = (const int*)d_in[3];
    const float* rconf = (const float*)d_in[4];
    const float* ent   = (const float*)d_in[5];
    const float* rel   = (const float*)d_in[6];
    const float* nv    = (const float*)d_in[7];

    int B   = in_sizes[0] / 3;
    int NEG = in_sizes[1] / 3;
    int NR  = in_sizes[2];

    int totalWarps = B + NEG;
    int blocks = (totalWarps * 32 + 255) / 256;

    dist_kernel<<<blocks, 256>>>(pos, neg, rr1, rr2, rconf, ent, rel, nv,
                                 (float*)d_out, B, NEG, NR);

    int rthreads = 256;
    int rblocks  = ((NEG >> 2) + rthreads - 1) / rthreads;
    if (rblocks < 1) rblocks = 1;
    final_reduce<<<rblocks, rthreads>>>((float*)d_out, B, NEG);
}